// round 15
// baseline (speedup 1.0000x reference)
#include <cuda_runtime.h>
#include <cuda_fp16.h>
#include <cstdint>

// ---------------- problem constants ----------------
#define Nn   10000
#define KRr  5
#define KAa  8
#define Cc   32
#define Oo   64

#define Mdim 40000            // B*N
#define Mpad 40064            // 313 * 128

// ---------------- frequency-block GEMM tiling ----------------
#define KF   320                   // K per freq block
#define NF   128                   // N per freq block
#define NBLK 4                     // {f0|f4}, f1, f2, f3
#define KCHUNK 64                  // fp16 per K chunk (128 B per row)
#define NCHUNK_F (KF / KCHUNK)     // 5
#define B_OFF 16384
#define STAGE_BYTES 32768
#define NSTAGE 3
#define GEMM_SMEM (NSTAGE * STAGE_BYTES)   // 98304 -> 2 CTAs/SM

#define SQH 0.70710678118654752f

// pipeline split: first stage covers m [0, 20096) = 157 gemm tiles = 628 gather blocks
#define G_BLKA 628
#define G_BLKB 622
#define T_A    157
#define T_B    156
#define C_BLKA 2512
#define C_BLKB 2488

// ---------------- device scratch ----------------
// X-hat physical layout: [j][m][32] halfs, j = comp*5 + p  (40 blocks)
__device__ __half g_Xh[(size_t)40 * Mpad * 32];
__device__ __half g_Wb[(size_t)NBLK * NF * KF];     // W-hat blocks [4][128][320]
__device__ __half g_Sh[(size_t)4 * Nn * Cc];        // signal fp16
__device__ __half g_Yh[(size_t)Mpad * 512];         // freq-domain GEMM output (fp16)
__device__ float  g_biasK[Oo];

// ---------------- helpers ----------------
__device__ __forceinline__ uint32_t smem_u32(const void* p) {
    uint32_t a;
    asm("{ .reg .u64 t; cvta.to.shared.u64 t, %1; cvt.u32.u64 %0, t; }" : "=r"(a) : "l"(p));
    return a;
}
__device__ __forceinline__ void cp16(uint32_t dst, const void* src) {
    asm volatile("cp.async.cg.shared.global [%0], [%1], 16;" :: "r"(dst), "l"(src));
}
__device__ __forceinline__ void ldsm_x4(uint32_t addr, uint32_t& r0, uint32_t& r1,
                                        uint32_t& r2, uint32_t& r3) {
    asm volatile("ldmatrix.sync.aligned.m8n8.x4.shared.b16 {%0,%1,%2,%3}, [%4];"
                 : "=r"(r0), "=r"(r1), "=r"(r2), "=r"(r3) : "r"(addr));
}
__device__ __forceinline__ void mma16816(float* c, const uint32_t* a,
                                         uint32_t b0, uint32_t b1) {
    asm volatile(
        "mma.sync.aligned.m16n8k16.row.col.f32.f16.f16.f32 "
        "{%0,%1,%2,%3}, {%4,%5,%6,%7}, {%8,%9}, {%0,%1,%2,%3};"
        : "+f"(c[0]), "+f"(c[1]), "+f"(c[2]), "+f"(c[3])
        : "r"(a[0]), "r"(a[1]), "r"(a[2]), "r"(a[3]), "r"(b0), "r"(b1));
}

// 8-point real DFT: x[0..7] -> {X0, X4, Re1, Im1, Re2, Im2, Re3, Im3}
__device__ __forceinline__ void fft8(const float* x, float* o) {
    float p04 = x[0] + x[4], m04 = x[0] - x[4];
    float p26 = x[2] + x[6], m26 = x[2] - x[6];
    float pbd = x[1] + x[3], pfh = x[5] + x[7];
    float mbd = x[1] - x[3], mfh = x[5] - x[7];
    float sodd = pbd + pfh;
    float B1 = mbd - mfh;
    float B2 = pfh - pbd;
    o[0] = p04 + p26 + sodd;
    o[1] = p04 + p26 - sodd;
    o[2] = m04 + SQH * B1;
    o[3] = -m26 + SQH * B2;
    o[4] = p04 - p26;
    o[5] = -(mbd + mfh);
    o[6] = m04 - SQH * B1;
    o[7] = m26 + SQH * B2;
}

// ---------------------------------------------------------------------------
// Merged prep: blocks 0..511 -> W-hat rows (+bias on block 0);
//              blocks 512..1511 -> signal fp16 conversion (320000 float4).
// ---------------------------------------------------------------------------
__global__ void __launch_bounds__(320)
prep_all_kernel(const float* __restrict__ signal,
                const float* __restrict__ kernels,
                const float* __restrict__ bias) {
    const int blk = blockIdx.x;
    if (blk < 512) {
        const int row = blk;                  // 0..511
        const int g = row >> 7;
        const int np = row & 127;
        const int h = np >> 6, o = np & 63;
        const int kp = threadIdx.x;           // 0..319
        const int half = (kp >= 160) ? 1 : 0;
        const int kk = kp - 160 * half;
        const int p = kk >> 5, c = kk & 31;

        float wsum[8];
#pragma unroll
        for (int q = 0; q < 8; q++) {
            int base = p * 16384 + q * 2048 + o * 32 + c;
            wsum[q] = kernels[base] + kernels[81920 + base];
        }

        float val = 0.f;
        if (g == 0) {
            if (h == 0 && half == 0) {
#pragma unroll
                for (int q = 0; q < 8; q++) val += wsum[q];
            } else if (h == 1 && half == 1) {
#pragma unroll
                for (int q = 0; q < 8; q++) val += (q & 1) ? -wsum[q] : wsum[q];
            }
        } else {
            const float ct[8] = {1.f, SQH, 0.f, -SQH, -1.f, -SQH, 0.f, SQH};
            const float st[8] = {0.f, SQH, 1.f, SQH, 0.f, -SQH, -1.f, -SQH};
            float Wr = 0.f, Wi = 0.f;
#pragma unroll
            for (int q = 0; q < 8; q++) {
                int i = (g * q) & 7;
                Wr += wsum[q] * ct[i];
                Wi -= wsum[q] * st[i];
            }
            if (h == 0) val = half ? Wi : Wr;
            else        val = half ? -Wr : Wi;
        }
        g_Wb[(size_t)row * KF + kp] = __float2half_rn(val);

        if (blk == 0 && threadIdx.x < 64) {
            int oo = threadIdx.x;
            float s = 0.f;
#pragma unroll
            for (int pq = 0; pq < KRr * KAa; pq++) s += bias[pq * Oo + oo];
            g_biasK[oo] = 2.0f * s;
        }
    } else {
        int i = (blk - 512) * 320 + threadIdx.x;          // float4 index
        if (i < (4 * Nn * Cc) / 4) {
            float4 v = ((const float4*)signal)[i];
            __half2 h0 = __halves2half2(__float2half_rn(v.x), __float2half_rn(v.y));
            __half2 h1 = __halves2half2(__float2half_rn(v.z), __float2half_rn(v.w));
            ((__half2*)g_Sh)[2 * i]     = h0;
            ((__half2*)g_Sh)[2 * i + 1] = h1;
        }
    }
}

// ---------------------------------------------------------------------------
// Gather + FFT -> X-hat fp16 (layout [j][m][32]); bary staged in SMEM.
// blk0: block offset for pipelined split.
// ---------------------------------------------------------------------------
__global__ void __launch_bounds__(256, 4)
gather_fft_kernel(const float* __restrict__ bary, int blk0) {
    __shared__ __align__(16) float sbary[32 * 240];   // 30720 B

    const int tid  = threadIdx.x;
    const int wid  = tid >> 5;
    const int lane = tid & 31;
    const int grp  = lane >> 3;
    const int sub  = lane & 7;

    const int m0blk = (blk0 + blockIdx.x) * 32;
    const int ml = wid * 4 + grp;          // local m in [0,32)
    const int m  = m0blk + ml;

    // stage bary block (coalesced)
    {
        const float4* src = (const float4*)(bary + (size_t)m0blk * 240);
        float4* dst = (float4*)sbary;
#pragma unroll
        for (int i = 0; i < 1920 / 256; i++)
            dst[tid + i * 256] = src[tid + i * 256];
        if (tid < 1920 - (1920 / 256) * 256)
            dst[tid + (1920 / 256) * 256] = src[tid + (1920 / 256) * 256];
    }
    __syncthreads();

    if (m >= Mdim) return;

    const int b = m / Nn;
    const uint2* sb = (const uint2*)(g_Sh + (size_t)b * (Nn * Cc));
    const float2* bm = (const float2*)(sbary + ml * 240);
    uint2* xg = (uint2*)g_Xh;              // [j][m][8] uint2 units

#pragma unroll
    for (int p = 0; p < KRr; p++) {
        float acc[8][4];
#pragma unroll
        for (int q = 0; q < 8; q++) {
            const float2* bb = bm + (p * 8 + q) * 3;
            float a0 = 0.f, a1 = 0.f, a2 = 0.f, a3 = 0.f;
#pragma unroll
            for (int v = 0; v < 3; v++) {
                float2 iw = bb[v];                 // ld.shared.v2 broadcast
                int idx = (int)iw.x;
                uint2 s = sb[idx * 8 + sub];
                float2 f0 = __half22float2(*(const __half2*)&s.x);
                float2 f1 = __half22float2(*(const __half2*)&s.y);
                a0 = fmaf(iw.y, f0.x, a0);
                a1 = fmaf(iw.y, f0.y, a1);
                a2 = fmaf(iw.y, f1.x, a2);
                a3 = fmaf(iw.y, f1.y, a3);
            }
            acc[q][0] = a0; acc[q][1] = a1; acc[q][2] = a2; acc[q][3] = a3;
        }
        float o[4][8];
#pragma unroll
        for (int j = 0; j < 4; j++) {
            float in[8];
#pragma unroll
            for (int q = 0; q < 8; q++) in[q] = acc[q][j];
            fft8(in, o[j]);
        }
#pragma unroll
        for (int comp = 0; comp < 8; comp++) {
            __half2 h0 = __halves2half2(__float2half_rn(o[0][comp]),
                                        __float2half_rn(o[1][comp]));
            __half2 h1 = __halves2half2(__float2half_rn(o[2][comp]),
                                        __float2half_rn(o[3][comp]));
            uint2 v;
            v.x = *(const uint32_t*)&h0;
            v.y = *(const uint32_t*)&h1;
            xg[((size_t)(comp * 5 + p) * Mpad + m) * 8 + sub] = v;
        }
    }
}

// ---------------------------------------------------------------------------
// HMMA GEMM per freq block; A read from [j][m][32] layout; Y written fp16.
// ty0: m-tile offset for pipelined split.
// ---------------------------------------------------------------------------
__global__ void __launch_bounds__(256, 2)
gemm_mma_kernel(int ty0) {
    extern __shared__ __align__(1024) char smem[];
    const uint32_t sb0 = smem_u32(smem);
    const int tid  = threadIdx.x;
    const int wid  = tid >> 5;
    const int lane = tid & 31;
    const int wm = wid & 3;
    const int wn = wid >> 2;

    const int g  = blockIdx.x;
    const int m0 = (ty0 + blockIdx.y) * 128;

    const int l_row = tid >> 3;
    const int l_seg = tid & 7;
    const uint32_t l_doff = l_row * 128 + ((l_seg ^ (l_row & 7)) << 4);
    const __half* aptr = g_Xh
        + ((size_t)(g * 10 + (l_seg >> 2)) * Mpad + m0 + l_row) * 32
        + (l_seg & 3) * 8;
    const __half* bptr = g_Wb + (size_t)(g * NF + l_row) * KF + l_seg * 8;

    auto load_stage = [&](int c) {
        const uint32_t sb = sb0 + (c % NSTAGE) * STAGE_BYTES;
        const __half* a = aptr + (size_t)(2 * c) * (Mpad * 32);
        const __half* b = bptr + c * KCHUNK;
#pragma unroll
        for (int i = 0; i < 4; i++) {
            uint32_t d = sb + l_doff + i * (32 * 128);
            cp16(d,         a + (size_t)(i * 32) * 32);
            cp16(d + B_OFF, b + (size_t)(i * 32) * KF);
        }
        asm volatile("cp.async.commit_group;" ::: "memory");
    };

    float acc[2][8][4];
#pragma unroll
    for (int mt = 0; mt < 2; mt++)
#pragma unroll
        for (int nt = 0; nt < 8; nt++)
#pragma unroll
            for (int i = 0; i < 4; i++) acc[mt][nt][i] = 0.f;

    const int sel = lane >> 4;
    uint32_t a_base[2], b_base[4];
#pragma unroll
    for (int mt = 0; mt < 2; mt++) {
        int r = wm * 32 + (lane & 15) + mt * 16;
        a_base[mt] = r * 128 + (((sel ^ r) & 7) << 4);
    }
#pragma unroll
    for (int bt = 0; bt < 4; bt++) {
        int r = wn * 64 + (lane & 15) + bt * 16;
        b_base[bt] = B_OFF + r * 128 + (((sel ^ r) & 7) << 4);
    }

    load_stage(0);
    load_stage(1);

    for (int c = 0; c < NCHUNK_F; c++) {
        if (c + 1 < NCHUNK_F) asm volatile("cp.async.wait_group 1;" ::: "memory");
        else                  asm volatile("cp.async.wait_group 0;" ::: "memory");
        __syncthreads();
        if (c + 2 < NCHUNK_F) load_stage(c + 2);

        const uint32_t sb = sb0 + (c % NSTAGE) * STAGE_BYTES;

#pragma unroll
        for (int ks = 0; ks < 4; ks++) {
            const uint32_t xv = ks << 5;
            uint32_t ah[2][4];
#pragma unroll
            for (int mt = 0; mt < 2; mt++)
                ldsm_x4((sb + a_base[mt]) ^ xv, ah[mt][0], ah[mt][1], ah[mt][2], ah[mt][3]);
            uint32_t bh[8][2];
#pragma unroll
            for (int bt = 0; bt < 4; bt++) {
                uint32_t r0, r1, r2, r3;
                ldsm_x4((sb + b_base[bt]) ^ xv, r0, r1, r2, r3);
                bh[2 * bt][0] = r0; bh[2 * bt][1] = r2;
                bh[2 * bt + 1][0] = r1; bh[2 * bt + 1][1] = r3;
            }
#pragma unroll
            for (int mt = 0; mt < 2; mt++)
#pragma unroll
                for (int nt = 0; nt < 8; nt++)
                    mma16816(acc[mt][nt], ah[mt], bh[nt][0], bh[nt][1]);
        }
    }

    const int ob = (lane & 3) * 2;
#pragma unroll
    for (int mt = 0; mt < 2; mt++) {
#pragma unroll
        for (int half = 0; half < 2; half++) {
            int m = m0 + wm * 32 + mt * 16 + (lane >> 2) + half * 8;
            __half* yp = g_Yh + (size_t)m * 512 + g * NF + wn * 64;
#pragma unroll
            for (int nt = 0; nt < 8; nt++) {
                __half2 hv = __floats2half2_rn(acc[mt][nt][half * 2 + 0],
                                               acc[mt][nt][half * 2 + 1]);
                *(__half2*)&yp[nt * 8 + ob] = hv;
            }
        }
    }
}

// ---------------------------------------------------------------------------
// Combine: inverse twiddle + bias, reading fp16 Y.  mb0: block offset.
// ---------------------------------------------------------------------------
__global__ void combine_kernel(float* __restrict__ out, int mb0) {
    const int m = (mb0 + blockIdx.x) * 8 + (threadIdx.x >> 5);
    if (m >= Mdim) return;
    const int lane = threadIdx.x & 31;

    const __half2* y2 = (const __half2*)(g_Yh + (size_t)m * 512);
    float2 Z0 = __half22float2(y2[lane]);
    float2 Z4 = __half22float2(y2[32 + lane]);
    float2 R1 = __half22float2(y2[64 + lane]);
    float2 I1 = __half22float2(y2[96 + lane]);
    float2 R2 = __half22float2(y2[128 + lane]);
    float2 I2 = __half22float2(y2[160 + lane]);
    float2 R3 = __half22float2(y2[192 + lane]);
    float2 I3 = __half22float2(y2[224 + lane]);

    const float bx = g_biasK[2 * lane];
    const float by = g_biasK[2 * lane + 1];

    const int b = m / Nn;
    const int n = m - b * Nn;
    float* op = out + (size_t)b * ((size_t)KAa * Nn * Oo) + (size_t)n * Oo + 2 * lane;

    const float C1[8] = {1.f, SQH, 0.f, -SQH, -1.f, -SQH, 0.f, SQH};
    const float S1[8] = {0.f, SQH, 1.f, SQH, 0.f, -SQH, -1.f, -SQH};
    const float C2[8] = {1.f, 0.f, -1.f, 0.f, 1.f, 0.f, -1.f, 0.f};
    const float S2[8] = {0.f, 1.f, 0.f, -1.f, 0.f, 1.f, 0.f, -1.f};
    const float C3[8] = {1.f, -SQH, 0.f, SQH, -1.f, SQH, 0.f, -SQH};
    const float S3[8] = {0.f, SQH, -1.f, SQH, 0.f, -SQH, 1.f, -SQH};

#pragma unroll
    for (int r = 0; r < 8; r++) {
        float sg = (r & 1) ? -1.f : 1.f;
        float2 v;
        v.x = 0.125f * (Z0.x + sg * Z4.x)
            + 0.25f * (C1[r] * R1.x - S1[r] * I1.x
                     + C2[r] * R2.x - S2[r] * I2.x
                     + C3[r] * R3.x - S3[r] * I3.x) + bx;
        v.y = 0.125f * (Z0.y + sg * Z4.y)
            + 0.25f * (C1[r] * R1.y - S1[r] * I1.y
                     + C2[r] * R2.y - S2[r] * I2.y
                     + C3[r] * R3.y - S3[r] * I3.y) + by;
        *(float2*)&op[(size_t)r * (Nn * Oo)] = v;
    }
}

// ---------------------------------------------------------------------------
extern "C" void kernel_launch(void* const* d_in, const int* in_sizes, int n_in,
                              void* d_out, int out_size) {
    const float* signal  = (const float*)d_in[0];
    const float* bary    = (const float*)d_in[1];
    const float* kernels = (const float*)d_in[2];
    const float* bias    = (const float*)d_in[3];
    float* out = (float*)d_out;

    static cudaStream_t s1 = nullptr;
    static cudaEvent_t evA = nullptr, evB = nullptr, evGA = nullptr, evCA = nullptr;
    if (!s1) {
        cudaStreamCreateWithFlags(&s1, cudaStreamNonBlocking);
        cudaEventCreateWithFlags(&evA,  cudaEventDisableTiming);
        cudaEventCreateWithFlags(&evB,  cudaEventDisableTiming);
        cudaEventCreateWithFlags(&evGA, cudaEventDisableTiming);
        cudaEventCreateWithFlags(&evCA, cudaEventDisableTiming);
        cudaFuncSetAttribute(gemm_mma_kernel,
                             cudaFuncAttributeMaxDynamicSharedMemorySize, GEMM_SMEM);
    }

    // stage 0: preps + gather A (first half of m)
    prep_all_kernel<<<512 + 1000, 320>>>(signal, kernels, bias);
    gather_fft_kernel<<<G_BLKA, 256>>>(bary, 0);
    cudaEventRecord(evA, 0);

    // fork: gather B on side stream, overlapping gemm A on main stream
    cudaStreamWaitEvent(s1, evA, 0);
    gather_fft_kernel<<<G_BLKB, 256, 0, s1>>>(bary, G_BLKA);
    cudaEventRecord(evB, s1);

    {
        dim3 grid(NBLK, T_A);
        gemm_mma_kernel<<<grid, 256, GEMM_SMEM>>>(0);
    }
    cudaEventRecord(evGA, 0);

    // combine A on side stream, overlapping gemm B on main stream
    cudaStreamWaitEvent(s1, evGA, 0);
    combine_kernel<<<C_BLKA, 256, 0, s1>>>(out, 0);
    cudaEventRecord(evCA, s1);

    cudaStreamWaitEvent(0, evB, 0);
    {
        dim3 grid(NBLK, T_B);
        gemm_mma_kernel<<<grid, 256, GEMM_SMEM>>>(T_A);
    }
    combine_kernel<<<C_BLKB, 256>>>(out, C_BLKA);

    // join
    cudaStreamWaitEvent(0, evCA, 0);
}

// round 16
// speedup vs baseline: 1.1233x; 1.1233x over previous
#include <cuda_runtime.h>
#include <cuda_fp16.h>
#include <cstdint>

// ---------------- problem constants ----------------
#define Nn   10000
#define KRr  5
#define KAa  8
#define Cc   32
#define Oo   64

#define Mdim 40000            // B*N
#define Mpad 40064            // 313 * 128

// ---------------- frequency-block GEMM tiling ----------------
#define KF   320                   // K per freq block
#define NF   128                   // N per freq block
#define NBLK 4                     // {f0|f4}, f1, f2, f3
#define KCHUNK 64                  // fp16 per K chunk (128 B per row)
#define NCHUNK_F (KF / KCHUNK)     // 5
#define B_OFF 16384
#define STAGE_BYTES 32768
#define NSTAGE 3
#define GEMM_SMEM (NSTAGE * STAGE_BYTES)   // 98304 -> 2 CTAs/SM

#define SQH 0.70710678118654752f

// ---------------- device scratch ----------------
// X-hat physical layout: [j][m][32] halfs, j = comp*5 + p  (40 blocks)
__device__ __half g_Xh[(size_t)40 * Mpad * 32];
__device__ __half g_Wb[(size_t)NBLK * NF * KF];     // W-hat blocks [4][128][320]
__device__ __half g_Sh[(size_t)4 * Nn * Cc];        // signal fp16
__device__ __half g_Yh[(size_t)Mpad * 512];         // freq-domain GEMM output (fp16)
__device__ float  g_biasK[Oo];

// ---------------- helpers ----------------
__device__ __forceinline__ uint32_t smem_u32(const void* p) {
    uint32_t a;
    asm("{ .reg .u64 t; cvta.to.shared.u64 t, %1; cvt.u32.u64 %0, t; }" : "=r"(a) : "l"(p));
    return a;
}
__device__ __forceinline__ void cp16(uint32_t dst, const void* src) {
    asm volatile("cp.async.cg.shared.global [%0], [%1], 16;" :: "r"(dst), "l"(src));
}
__device__ __forceinline__ void ldsm_x4(uint32_t addr, uint32_t& r0, uint32_t& r1,
                                        uint32_t& r2, uint32_t& r3) {
    asm volatile("ldmatrix.sync.aligned.m8n8.x4.shared.b16 {%0,%1,%2,%3}, [%4];"
                 : "=r"(r0), "=r"(r1), "=r"(r2), "=r"(r3) : "r"(addr));
}
__device__ __forceinline__ void mma16816(float* c, const uint32_t* a,
                                         uint32_t b0, uint32_t b1) {
    asm volatile(
        "mma.sync.aligned.m16n8k16.row.col.f32.f16.f16.f32 "
        "{%0,%1,%2,%3}, {%4,%5,%6,%7}, {%8,%9}, {%0,%1,%2,%3};"
        : "+f"(c[0]), "+f"(c[1]), "+f"(c[2]), "+f"(c[3])
        : "r"(a[0]), "r"(a[1]), "r"(a[2]), "r"(a[3]), "r"(b0), "r"(b1));
}

// 8-point real DFT: x[0..7] -> {X0, X4, Re1, Im1, Re2, Im2, Re3, Im3}
__device__ __forceinline__ void fft8(const float* x, float* o) {
    float p04 = x[0] + x[4], m04 = x[0] - x[4];
    float p26 = x[2] + x[6], m26 = x[2] - x[6];
    float pbd = x[1] + x[3], pfh = x[5] + x[7];
    float mbd = x[1] - x[3], mfh = x[5] - x[7];
    float sodd = pbd + pfh;
    float B1 = mbd - mfh;
    float B2 = pfh - pbd;
    o[0] = p04 + p26 + sodd;
    o[1] = p04 + p26 - sodd;
    o[2] = m04 + SQH * B1;
    o[3] = -m26 + SQH * B2;
    o[4] = p04 - p26;
    o[5] = -(mbd + mfh);
    o[6] = m04 - SQH * B1;
    o[7] = m26 + SQH * B2;
}

// ---------------------------------------------------------------------------
// Merged prep: blocks 0..511 -> W-hat rows (+bias on block 0);
//              blocks 512..1511 -> signal fp16 conversion (320000 float4).
// ---------------------------------------------------------------------------
__global__ void __launch_bounds__(320)
prep_all_kernel(const float* __restrict__ signal,
                const float* __restrict__ kernels,
                const float* __restrict__ bias) {
    const int blk = blockIdx.x;
    if (blk < 512) {
        const int row = blk;                  // 0..511
        const int g = row >> 7;
        const int np = row & 127;
        const int h = np >> 6, o = np & 63;
        const int kp = threadIdx.x;           // 0..319
        const int half = (kp >= 160) ? 1 : 0;
        const int kk = kp - 160 * half;
        const int p = kk >> 5, c = kk & 31;

        float wsum[8];
#pragma unroll
        for (int q = 0; q < 8; q++) {
            int base = p * 16384 + q * 2048 + o * 32 + c;
            wsum[q] = kernels[base] + kernels[81920 + base];
        }

        float val = 0.f;
        if (g == 0) {
            if (h == 0 && half == 0) {
#pragma unroll
                for (int q = 0; q < 8; q++) val += wsum[q];
            } else if (h == 1 && half == 1) {
#pragma unroll
                for (int q = 0; q < 8; q++) val += (q & 1) ? -wsum[q] : wsum[q];
            }
        } else {
            const float ct[8] = {1.f, SQH, 0.f, -SQH, -1.f, -SQH, 0.f, SQH};
            const float st[8] = {0.f, SQH, 1.f, SQH, 0.f, -SQH, -1.f, -SQH};
            float Wr = 0.f, Wi = 0.f;
#pragma unroll
            for (int q = 0; q < 8; q++) {
                int i = (g * q) & 7;
                Wr += wsum[q] * ct[i];
                Wi -= wsum[q] * st[i];
            }
            if (h == 0) val = half ? Wi : Wr;
            else        val = half ? -Wr : Wi;
        }
        g_Wb[(size_t)row * KF + kp] = __float2half_rn(val);

        if (blk == 0 && threadIdx.x < 64) {
            int oo = threadIdx.x;
            float s = 0.f;
#pragma unroll
            for (int pq = 0; pq < KRr * KAa; pq++) s += bias[pq * Oo + oo];
            g_biasK[oo] = 2.0f * s;
        }
    } else {
        int i = (blk - 512) * 320 + threadIdx.x;          // float4 index
        if (i < (4 * Nn * Cc) / 4) {
            float4 v = ((const float4*)signal)[i];
            __half2 h0 = __halves2half2(__float2half_rn(v.x), __float2half_rn(v.y));
            __half2 h1 = __halves2half2(__float2half_rn(v.z), __float2half_rn(v.w));
            ((__half2*)g_Sh)[2 * i]     = h0;
            ((__half2*)g_Sh)[2 * i + 1] = h1;
        }
    }
}

// ---------------------------------------------------------------------------
// Gather + FFT -> X-hat fp16 (layout [j][m][32]); bary staged in SMEM.
// ---------------------------------------------------------------------------
__global__ void __launch_bounds__(256, 4)
gather_fft_kernel(const float* __restrict__ bary) {
    __shared__ __align__(16) float sbary[32 * 240];   // 30720 B

    const int tid  = threadIdx.x;
    const int wid  = tid >> 5;
    const int lane = tid & 31;
    const int grp  = lane >> 3;
    const int sub  = lane & 7;

    const int m0blk = blockIdx.x * 32;
    const int ml = wid * 4 + grp;          // local m in [0,32)
    const int m  = m0blk + ml;

    // stage bary block (coalesced)
    {
        const float4* src = (const float4*)(bary + (size_t)m0blk * 240);
        float4* dst = (float4*)sbary;
#pragma unroll
        for (int i = 0; i < 1920 / 256; i++)
            dst[tid + i * 256] = src[tid + i * 256];
        if (tid < 1920 - (1920 / 256) * 256)
            dst[tid + (1920 / 256) * 256] = src[tid + (1920 / 256) * 256];
    }
    __syncthreads();

    const int b = m / Nn;
    const uint2* sb = (const uint2*)(g_Sh + (size_t)b * (Nn * Cc));
    const float2* bm = (const float2*)(sbary + ml * 240);
    uint2* xg = (uint2*)g_Xh;              // [j][m][8] uint2 units

#pragma unroll
    for (int p = 0; p < KRr; p++) {
        float acc[8][4];
#pragma unroll
        for (int q = 0; q < 8; q++) {
            const float2* bb = bm + (p * 8 + q) * 3;
            float a0 = 0.f, a1 = 0.f, a2 = 0.f, a3 = 0.f;
#pragma unroll
            for (int v = 0; v < 3; v++) {
                float2 iw = bb[v];                 // ld.shared.v2 broadcast
                int idx = (int)iw.x;
                uint2 s = sb[idx * 8 + sub];
                float2 f0 = __half22float2(*(const __half2*)&s.x);
                float2 f1 = __half22float2(*(const __half2*)&s.y);
                a0 = fmaf(iw.y, f0.x, a0);
                a1 = fmaf(iw.y, f0.y, a1);
                a2 = fmaf(iw.y, f1.x, a2);
                a3 = fmaf(iw.y, f1.y, a3);
            }
            acc[q][0] = a0; acc[q][1] = a1; acc[q][2] = a2; acc[q][3] = a3;
        }
        float o[4][8];
#pragma unroll
        for (int j = 0; j < 4; j++) {
            float in[8];
#pragma unroll
            for (int q = 0; q < 8; q++) in[q] = acc[q][j];
            fft8(in, o[j]);
        }
#pragma unroll
        for (int comp = 0; comp < 8; comp++) {
            __half2 h0 = __halves2half2(__float2half_rn(o[0][comp]),
                                        __float2half_rn(o[1][comp]));
            __half2 h1 = __halves2half2(__float2half_rn(o[2][comp]),
                                        __float2half_rn(o[3][comp]));
            uint2 v;
            v.x = *(const uint32_t*)&h0;
            v.y = *(const uint32_t*)&h1;
            xg[((size_t)(comp * 5 + p) * Mpad + m) * 8 + sub] = v;
        }
    }
}

// ---------------------------------------------------------------------------
// HMMA GEMM per freq block; A read from [j][m][32] layout; Y written fp16.
// ---------------------------------------------------------------------------
__global__ void __launch_bounds__(256, 2)
gemm_mma_kernel() {
    extern __shared__ __align__(1024) char smem[];
    const uint32_t sb0 = smem_u32(smem);
    const int tid  = threadIdx.x;
    const int wid  = tid >> 5;
    const int lane = tid & 31;
    const int wm = wid & 3;
    const int wn = wid >> 2;

    const int g  = blockIdx.x;
    const int m0 = blockIdx.y * 128;

    const int l_row = tid >> 3;
    const int l_seg = tid & 7;
    const uint32_t l_doff = l_row * 128 + ((l_seg ^ (l_row & 7)) << 4);
    const __half* aptr = g_Xh
        + ((size_t)(g * 10 + (l_seg >> 2)) * Mpad + m0 + l_row) * 32
        + (l_seg & 3) * 8;
    const __half* bptr = g_Wb + (size_t)(g * NF + l_row) * KF + l_seg * 8;

    auto load_stage = [&](int c) {
        const uint32_t sb = sb0 + (c % NSTAGE) * STAGE_BYTES;
        const __half* a = aptr + (size_t)(2 * c) * (Mpad * 32);
        const __half* b = bptr + c * KCHUNK;
#pragma unroll
        for (int i = 0; i < 4; i++) {
            uint32_t d = sb + l_doff + i * (32 * 128);
            cp16(d,         a + (size_t)(i * 32) * 32);
            cp16(d + B_OFF, b + (size_t)(i * 32) * KF);
        }
        asm volatile("cp.async.commit_group;" ::: "memory");
    };

    float acc[2][8][4];
#pragma unroll
    for (int mt = 0; mt < 2; mt++)
#pragma unroll
        for (int nt = 0; nt < 8; nt++)
#pragma unroll
            for (int i = 0; i < 4; i++) acc[mt][nt][i] = 0.f;

    const int sel = lane >> 4;
    uint32_t a_base[2], b_base[4];
#pragma unroll
    for (int mt = 0; mt < 2; mt++) {
        int r = wm * 32 + (lane & 15) + mt * 16;
        a_base[mt] = r * 128 + (((sel ^ r) & 7) << 4);
    }
#pragma unroll
    for (int bt = 0; bt < 4; bt++) {
        int r = wn * 64 + (lane & 15) + bt * 16;
        b_base[bt] = B_OFF + r * 128 + (((sel ^ r) & 7) << 4);
    }

    load_stage(0);
    load_stage(1);

    for (int c = 0; c < NCHUNK_F; c++) {
        if (c + 1 < NCHUNK_F) asm volatile("cp.async.wait_group 1;" ::: "memory");
        else                  asm volatile("cp.async.wait_group 0;" ::: "memory");
        __syncthreads();
        if (c + 2 < NCHUNK_F) load_stage(c + 2);

        const uint32_t sb = sb0 + (c % NSTAGE) * STAGE_BYTES;

#pragma unroll
        for (int ks = 0; ks < 4; ks++) {
            const uint32_t xv = ks << 5;
            uint32_t ah[2][4];
#pragma unroll
            for (int mt = 0; mt < 2; mt++)
                ldsm_x4((sb + a_base[mt]) ^ xv, ah[mt][0], ah[mt][1], ah[mt][2], ah[mt][3]);
            uint32_t bh[8][2];
#pragma unroll
            for (int bt = 0; bt < 4; bt++) {
                uint32_t r0, r1, r2, r3;
                ldsm_x4((sb + b_base[bt]) ^ xv, r0, r1, r2, r3);
                bh[2 * bt][0] = r0; bh[2 * bt][1] = r2;
                bh[2 * bt + 1][0] = r1; bh[2 * bt + 1][1] = r3;
            }
#pragma unroll
            for (int mt = 0; mt < 2; mt++)
#pragma unroll
                for (int nt = 0; nt < 8; nt++)
                    mma16816(acc[mt][nt], ah[mt], bh[nt][0], bh[nt][1]);
        }
    }

    const int ob = (lane & 3) * 2;
#pragma unroll
    for (int mt = 0; mt < 2; mt++) {
#pragma unroll
        for (int half = 0; half < 2; half++) {
            int m = m0 + wm * 32 + mt * 16 + (lane >> 2) + half * 8;
            __half* yp = g_Yh + (size_t)m * 512 + g * NF + wn * 64;
#pragma unroll
            for (int nt = 0; nt < 8; nt++) {
                __half2 hv = __floats2half2_rn(acc[mt][nt][half * 2 + 0],
                                               acc[mt][nt][half * 2 + 1]);
                *(__half2*)&yp[nt * 8 + ob] = hv;
            }
        }
    }
}

// ---------------------------------------------------------------------------
// Combine v2: warp covers 2 m-rows (16 lanes each); each lane owns an o-quad.
// Y loads: uint2 (8B); out stores: float4 (16B, warp-contiguous 256B per (m,r)).
// ---------------------------------------------------------------------------
__global__ void __launch_bounds__(256)
combine_kernel(float* __restrict__ out) {
    const int warp = blockIdx.x * 8 + (threadIdx.x >> 5);
    const int lane = threadIdx.x & 31;
    const int m = warp * 2 + (lane >> 4);
    if (m >= Mdim) return;
    const int oq = (lane & 15) * 4;          // o-quad base

    const uint2* y = (const uint2*)(g_Yh + (size_t)m * 512);
    float v[8][4];
#pragma unroll
    for (int comp = 0; comp < 8; comp++) {
        uint2 u = y[comp * 16 + (oq >> 2)];
        float2 a0 = __half22float2(*(const __half2*)&u.x);
        float2 a1 = __half22float2(*(const __half2*)&u.y);
        v[comp][0] = a0.x; v[comp][1] = a0.y;
        v[comp][2] = a1.x; v[comp][3] = a1.y;
    }

    const float4 b4 = *(const float4*)&g_biasK[oq];
    const float bs[4] = {b4.x, b4.y, b4.z, b4.w};

    const int b = m / Nn;
    const int n = m - b * Nn;
    float* op = out + (size_t)b * ((size_t)KAa * Nn * Oo) + (size_t)n * Oo + oq;

    const float C1[8] = {1.f, SQH, 0.f, -SQH, -1.f, -SQH, 0.f, SQH};
    const float S1[8] = {0.f, SQH, 1.f, SQH, 0.f, -SQH, -1.f, -SQH};
    const float C2[8] = {1.f, 0.f, -1.f, 0.f, 1.f, 0.f, -1.f, 0.f};
    const float S2[8] = {0.f, 1.f, 0.f, -1.f, 0.f, 1.f, 0.f, -1.f};
    const float C3[8] = {1.f, -SQH, 0.f, SQH, -1.f, SQH, 0.f, -SQH};
    const float S3[8] = {0.f, SQH, -1.f, SQH, 0.f, -SQH, 1.f, -SQH};

#pragma unroll
    for (int r = 0; r < 8; r++) {
        float sg = (r & 1) ? -1.f : 1.f;
        float4 w;
        float res[4];
#pragma unroll
        for (int i = 0; i < 4; i++) {
            res[i] = 0.125f * (v[0][i] + sg * v[1][i])
                   + 0.25f * (C1[r] * v[2][i] - S1[r] * v[3][i]
                            + C2[r] * v[4][i] - S2[r] * v[5][i]
                            + C3[r] * v[6][i] - S3[r] * v[7][i]) + bs[i];
        }
        w.x = res[0]; w.y = res[1]; w.z = res[2]; w.w = res[3];
        *(float4*)&op[(size_t)r * (Nn * Oo)] = w;
    }
}

// ---------------------------------------------------------------------------
extern "C" void kernel_launch(void* const* d_in, const int* in_sizes, int n_in,
                              void* d_out, int out_size) {
    const float* signal  = (const float*)d_in[0];
    const float* bary    = (const float*)d_in[1];
    const float* kernels = (const float*)d_in[2];
    const float* bias    = (const float*)d_in[3];
    float* out = (float*)d_out;

    // merged preps: 512 wb blocks + 1000 signal-conversion blocks (320000 float4)
    prep_all_kernel<<<512 + 1000, 320>>>(signal, kernels, bias);

    gather_fft_kernel<<<Mdim / 32, 256>>>(bary);

    {
        static int smem_set = 0;
        if (!smem_set) {
            cudaFuncSetAttribute(gemm_mma_kernel,
                                 cudaFuncAttributeMaxDynamicSharedMemorySize, GEMM_SMEM);
            smem_set = 1;
        }
        dim3 grid(NBLK, Mpad / 128);   // (4, 313)
        gemm_mma_kernel<<<grid, 256, GEMM_SMEM>>>();
    }

    // warp = 2 m rows -> 16 m per CTA -> 2500 blocks
    combine_kernel<<<Mdim / 16, 256>>>(out);
}

// round 17
// speedup vs baseline: 1.1466x; 1.0207x over previous
#include <cuda_runtime.h>
#include <cuda_fp16.h>
#include <cstdint>

// ---------------- problem constants ----------------
#define Nn   10000
#define KRr  5
#define KAa  8
#define Cc   32
#define Oo   64

#define Mdim 40000            // B*N
#define Mpad 40064            // 313 * 128

// ---------------- frequency-block GEMM tiling ----------------
#define KF   320                   // K per freq block
#define NF   128                   // N per freq block
#define NBLK 4                     // {f0|f4}, f1, f2, f3
#define KCHUNK 64                  // fp16 per K chunk (128 B per row)
#define NCHUNK_F (KF / KCHUNK)     // 5
#define B_OFF 16384
#define STAGE_BYTES 32768
#define NSTAGE 3
#define GEMM_SMEM (NSTAGE * STAGE_BYTES)   // 98304 -> 2 CTAs/SM

#define SQH 0.70710678118654752f

// ---------------- device scratch ----------------
// X-hat physical layout: [j][m][32] halfs, j = comp*5 + p  (40 blocks)
__device__ __half g_Xh[(size_t)40 * Mpad * 32];
__device__ __half g_Wb[(size_t)NBLK * NF * KF];     // W-hat blocks [4][128][320]
__device__ __half g_Sh[(size_t)4 * Nn * Cc];        // signal fp16
__device__ __half g_Yh[(size_t)Mpad * 512];         // freq-domain GEMM output (fp16)
__device__ float  g_biasK[Oo];

// ---------------- helpers ----------------
__device__ __forceinline__ uint32_t smem_u32(const void* p) {
    uint32_t a;
    asm("{ .reg .u64 t; cvta.to.shared.u64 t, %1; cvt.u32.u64 %0, t; }" : "=r"(a) : "l"(p));
    return a;
}
__device__ __forceinline__ void cp16(uint32_t dst, const void* src) {
    asm volatile("cp.async.cg.shared.global [%0], [%1], 16;" :: "r"(dst), "l"(src));
}
__device__ __forceinline__ void stg_cs_v2(void* p, uint2 v) {
    asm volatile("st.global.cs.v2.u32 [%0], {%1, %2};"
                 :: "l"(p), "r"(v.x), "r"(v.y) : "memory");
}
__device__ __forceinline__ void stg_cs_v4(void* p, float4 v) {
    asm volatile("st.global.cs.v4.f32 [%0], {%1, %2, %3, %4};"
                 :: "l"(p), "f"(v.x), "f"(v.y), "f"(v.z), "f"(v.w) : "memory");
}
__device__ __forceinline__ void ldsm_x4(uint32_t addr, uint32_t& r0, uint32_t& r1,
                                        uint32_t& r2, uint32_t& r3) {
    asm volatile("ldmatrix.sync.aligned.m8n8.x4.shared.b16 {%0,%1,%2,%3}, [%4];"
                 : "=r"(r0), "=r"(r1), "=r"(r2), "=r"(r3) : "r"(addr));
}
__device__ __forceinline__ void mma16816(float* c, const uint32_t* a,
                                         uint32_t b0, uint32_t b1) {
    asm volatile(
        "mma.sync.aligned.m16n8k16.row.col.f32.f16.f16.f32 "
        "{%0,%1,%2,%3}, {%4,%5,%6,%7}, {%8,%9}, {%0,%1,%2,%3};"
        : "+f"(c[0]), "+f"(c[1]), "+f"(c[2]), "+f"(c[3])
        : "r"(a[0]), "r"(a[1]), "r"(a[2]), "r"(a[3]), "r"(b0), "r"(b1));
}

// 8-point real DFT: x[0..7] -> {X0, X4, Re1, Im1, Re2, Im2, Re3, Im3}
__device__ __forceinline__ void fft8(const float* x, float* o) {
    float p04 = x[0] + x[4], m04 = x[0] - x[4];
    float p26 = x[2] + x[6], m26 = x[2] - x[6];
    float pbd = x[1] + x[3], pfh = x[5] + x[7];
    float mbd = x[1] - x[3], mfh = x[5] - x[7];
    float sodd = pbd + pfh;
    float B1 = mbd - mfh;
    float B2 = pfh - pbd;
    o[0] = p04 + p26 + sodd;
    o[1] = p04 + p26 - sodd;
    o[2] = m04 + SQH * B1;
    o[3] = -m26 + SQH * B2;
    o[4] = p04 - p26;
    o[5] = -(mbd + mfh);
    o[6] = m04 - SQH * B1;
    o[7] = m26 + SQH * B2;
}

// ---------------------------------------------------------------------------
// Merged prep: blocks 0..511 -> W-hat rows (+bias on block 0);
//              blocks 512..1511 -> signal fp16 conversion (320000 float4).
// ---------------------------------------------------------------------------
__global__ void __launch_bounds__(320)
prep_all_kernel(const float* __restrict__ signal,
                const float* __restrict__ kernels,
                const float* __restrict__ bias) {
    const int blk = blockIdx.x;
    if (blk < 512) {
        const int row = blk;                  // 0..511
        const int g = row >> 7;
        const int np = row & 127;
        const int h = np >> 6, o = np & 63;
        const int kp = threadIdx.x;           // 0..319
        const int half = (kp >= 160) ? 1 : 0;
        const int kk = kp - 160 * half;
        const int p = kk >> 5, c = kk & 31;

        float wsum[8];
#pragma unroll
        for (int q = 0; q < 8; q++) {
            int base = p * 16384 + q * 2048 + o * 32 + c;
            wsum[q] = kernels[base] + kernels[81920 + base];
        }

        float val = 0.f;
        if (g == 0) {
            if (h == 0 && half == 0) {
#pragma unroll
                for (int q = 0; q < 8; q++) val += wsum[q];
            } else if (h == 1 && half == 1) {
#pragma unroll
                for (int q = 0; q < 8; q++) val += (q & 1) ? -wsum[q] : wsum[q];
            }
        } else {
            const float ct[8] = {1.f, SQH, 0.f, -SQH, -1.f, -SQH, 0.f, SQH};
            const float st[8] = {0.f, SQH, 1.f, SQH, 0.f, -SQH, -1.f, -SQH};
            float Wr = 0.f, Wi = 0.f;
#pragma unroll
            for (int q = 0; q < 8; q++) {
                int i = (g * q) & 7;
                Wr += wsum[q] * ct[i];
                Wi -= wsum[q] * st[i];
            }
            if (h == 0) val = half ? Wi : Wr;
            else        val = half ? -Wr : Wi;
        }
        g_Wb[(size_t)row * KF + kp] = __float2half_rn(val);

        if (blk == 0 && threadIdx.x < 64) {
            int oo = threadIdx.x;
            float s = 0.f;
#pragma unroll
            for (int pq = 0; pq < KRr * KAa; pq++) s += bias[pq * Oo + oo];
            g_biasK[oo] = 2.0f * s;
        }
    } else {
        int i = (blk - 512) * 320 + threadIdx.x;          // float4 index
        if (i < (4 * Nn * Cc) / 4) {
            float4 v = ((const float4*)signal)[i];
            __half2 h0 = __halves2half2(__float2half_rn(v.x), __float2half_rn(v.y));
            __half2 h1 = __halves2half2(__float2half_rn(v.z), __float2half_rn(v.w));
            ((__half2*)g_Sh)[2 * i]     = h0;
            ((__half2*)g_Sh)[2 * i + 1] = h1;
        }
    }
}

// ---------------------------------------------------------------------------
// Gather + FFT -> X-hat fp16 (layout [j][m][32]); bary staged in SMEM.
// X-hat stores use .cs (evict-first) so the L2 keeps the signal working set.
// ---------------------------------------------------------------------------
__global__ void __launch_bounds__(256, 4)
gather_fft_kernel(const float* __restrict__ bary) {
    __shared__ __align__(16) float sbary[32 * 240];   // 30720 B

    const int tid  = threadIdx.x;
    const int wid  = tid >> 5;
    const int lane = tid & 31;
    const int grp  = lane >> 3;
    const int sub  = lane & 7;

    const int m0blk = blockIdx.x * 32;
    const int ml = wid * 4 + grp;          // local m in [0,32)
    const int m  = m0blk + ml;

    // stage bary block (coalesced)
    {
        const float4* src = (const float4*)(bary + (size_t)m0blk * 240);
        float4* dst = (float4*)sbary;
#pragma unroll
        for (int i = 0; i < 1920 / 256; i++)
            dst[tid + i * 256] = src[tid + i * 256];
        if (tid < 1920 - (1920 / 256) * 256)
            dst[tid + (1920 / 256) * 256] = src[tid + (1920 / 256) * 256];
    }
    __syncthreads();

    const int b = m / Nn;
    const uint2* sb = (const uint2*)(g_Sh + (size_t)b * (Nn * Cc));
    const float2* bm = (const float2*)(sbary + ml * 240);
    uint2* xg = (uint2*)g_Xh;              // [j][m][8] uint2 units

#pragma unroll
    for (int p = 0; p < KRr; p++) {
        float acc[8][4];
#pragma unroll
        for (int q = 0; q < 8; q++) {
            const float2* bb = bm + (p * 8 + q) * 3;
            float a0 = 0.f, a1 = 0.f, a2 = 0.f, a3 = 0.f;
#pragma unroll
            for (int v = 0; v < 3; v++) {
                float2 iw = bb[v];                 // ld.shared.v2 broadcast
                int idx = (int)iw.x;
                uint2 s = sb[idx * 8 + sub];
                float2 f0 = __half22float2(*(const __half2*)&s.x);
                float2 f1 = __half22float2(*(const __half2*)&s.y);
                a0 = fmaf(iw.y, f0.x, a0);
                a1 = fmaf(iw.y, f0.y, a1);
                a2 = fmaf(iw.y, f1.x, a2);
                a3 = fmaf(iw.y, f1.y, a3);
            }
            acc[q][0] = a0; acc[q][1] = a1; acc[q][2] = a2; acc[q][3] = a3;
        }
        float o[4][8];
#pragma unroll
        for (int j = 0; j < 4; j++) {
            float in[8];
#pragma unroll
            for (int q = 0; q < 8; q++) in[q] = acc[q][j];
            fft8(in, o[j]);
        }
#pragma unroll
        for (int comp = 0; comp < 8; comp++) {
            __half2 h0 = __halves2half2(__float2half_rn(o[0][comp]),
                                        __float2half_rn(o[1][comp]));
            __half2 h1 = __halves2half2(__float2half_rn(o[2][comp]),
                                        __float2half_rn(o[3][comp]));
            uint2 v;
            v.x = *(const uint32_t*)&h0;
            v.y = *(const uint32_t*)&h1;
            stg_cs_v2(&xg[((size_t)(comp * 5 + p) * Mpad + m) * 8 + sub], v);
        }
    }
}

// ---------------------------------------------------------------------------
// HMMA GEMM per freq block; A read from [j][m][32] layout; Y written fp16
// (default policy: combine wants Y L2-resident).
// ---------------------------------------------------------------------------
__global__ void __launch_bounds__(256, 2)
gemm_mma_kernel() {
    extern __shared__ __align__(1024) char smem[];
    const uint32_t sb0 = smem_u32(smem);
    const int tid  = threadIdx.x;
    const int wid  = tid >> 5;
    const int lane = tid & 31;
    const int wm = wid & 3;
    const int wn = wid >> 2;

    const int g  = blockIdx.x;
    const int m0 = blockIdx.y * 128;

    const int l_row = tid >> 3;
    const int l_seg = tid & 7;
    const uint32_t l_doff = l_row * 128 + ((l_seg ^ (l_row & 7)) << 4);
    const __half* aptr = g_Xh
        + ((size_t)(g * 10 + (l_seg >> 2)) * Mpad + m0 + l_row) * 32
        + (l_seg & 3) * 8;
    const __half* bptr = g_Wb + (size_t)(g * NF + l_row) * KF + l_seg * 8;

    auto load_stage = [&](int c) {
        const uint32_t sb = sb0 + (c % NSTAGE) * STAGE_BYTES;
        const __half* a = aptr + (size_t)(2 * c) * (Mpad * 32);
        const __half* b = bptr + c * KCHUNK;
#pragma unroll
        for (int i = 0; i < 4; i++) {
            uint32_t d = sb + l_doff + i * (32 * 128);
            cp16(d,         a + (size_t)(i * 32) * 32);
            cp16(d + B_OFF, b + (size_t)(i * 32) * KF);
        }
        asm volatile("cp.async.commit_group;" ::: "memory");
    };

    float acc[2][8][4];
#pragma unroll
    for (int mt = 0; mt < 2; mt++)
#pragma unroll
        for (int nt = 0; nt < 8; nt++)
#pragma unroll
            for (int i = 0; i < 4; i++) acc[mt][nt][i] = 0.f;

    const int sel = lane >> 4;
    uint32_t a_base[2], b_base[4];
#pragma unroll
    for (int mt = 0; mt < 2; mt++) {
        int r = wm * 32 + (lane & 15) + mt * 16;
        a_base[mt] = r * 128 + (((sel ^ r) & 7) << 4);
    }
#pragma unroll
    for (int bt = 0; bt < 4; bt++) {
        int r = wn * 64 + (lane & 15) + bt * 16;
        b_base[bt] = B_OFF + r * 128 + (((sel ^ r) & 7) << 4);
    }

    load_stage(0);
    load_stage(1);

    for (int c = 0; c < NCHUNK_F; c++) {
        if (c + 1 < NCHUNK_F) asm volatile("cp.async.wait_group 1;" ::: "memory");
        else                  asm volatile("cp.async.wait_group 0;" ::: "memory");
        __syncthreads();
        if (c + 2 < NCHUNK_F) load_stage(c + 2);

        const uint32_t sb = sb0 + (c % NSTAGE) * STAGE_BYTES;

#pragma unroll
        for (int ks = 0; ks < 4; ks++) {
            const uint32_t xv = ks << 5;
            uint32_t ah[2][4];
#pragma unroll
            for (int mt = 0; mt < 2; mt++)
                ldsm_x4((sb + a_base[mt]) ^ xv, ah[mt][0], ah[mt][1], ah[mt][2], ah[mt][3]);
            uint32_t bh[8][2];
#pragma unroll
            for (int bt = 0; bt < 4; bt++) {
                uint32_t r0, r1, r2, r3;
                ldsm_x4((sb + b_base[bt]) ^ xv, r0, r1, r2, r3);
                bh[2 * bt][0] = r0; bh[2 * bt][1] = r2;
                bh[2 * bt + 1][0] = r1; bh[2 * bt + 1][1] = r3;
            }
#pragma unroll
            for (int mt = 0; mt < 2; mt++)
#pragma unroll
                for (int nt = 0; nt < 8; nt++)
                    mma16816(acc[mt][nt], ah[mt], bh[nt][0], bh[nt][1]);
        }
    }

    const int ob = (lane & 3) * 2;
#pragma unroll
    for (int mt = 0; mt < 2; mt++) {
#pragma unroll
        for (int half = 0; half < 2; half++) {
            int m = m0 + wm * 32 + mt * 16 + (lane >> 2) + half * 8;
            __half* yp = g_Yh + (size_t)m * 512 + g * NF + wn * 64;
#pragma unroll
            for (int nt = 0; nt < 8; nt++) {
                __half2 hv = __floats2half2_rn(acc[mt][nt][half * 2 + 0],
                                               acc[mt][nt][half * 2 + 1]);
                *(__half2*)&yp[nt * 8 + ob] = hv;
            }
        }
    }
}

// ---------------------------------------------------------------------------
// Combine: warp covers 2 m-rows; lane owns an o-quad. Y reads L2-hot;
// out stores use .cs (evict-first) to keep Y resident.
// ---------------------------------------------------------------------------
__global__ void __launch_bounds__(256)
combine_kernel(float* __restrict__ out) {
    const int warp = blockIdx.x * 8 + (threadIdx.x >> 5);
    const int lane = threadIdx.x & 31;
    const int m = warp * 2 + (lane >> 4);
    if (m >= Mdim) return;
    const int oq = (lane & 15) * 4;          // o-quad base

    const uint2* y = (const uint2*)(g_Yh + (size_t)m * 512);
    float v[8][4];
#pragma unroll
    for (int comp = 0; comp < 8; comp++) {
        uint2 u = y[comp * 16 + (oq >> 2)];
        float2 a0 = __half22float2(*(const __half2*)&u.x);
        float2 a1 = __half22float2(*(const __half2*)&u.y);
        v[comp][0] = a0.x; v[comp][1] = a0.y;
        v[comp][2] = a1.x; v[comp][3] = a1.y;
    }

    const float4 b4 = *(const float4*)&g_biasK[oq];
    const float bs[4] = {b4.x, b4.y, b4.z, b4.w};

    const int b = m / Nn;
    const int n = m - b * Nn;
    float* op = out + (size_t)b * ((size_t)KAa * Nn * Oo) + (size_t)n * Oo + oq;

    const float C1[8] = {1.f, SQH, 0.f, -SQH, -1.f, -SQH, 0.f, SQH};
    const float S1[8] = {0.f, SQH, 1.f, SQH, 0.f, -SQH, -1.f, -SQH};
    const float C2[8] = {1.f, 0.f, -1.f, 0.f, 1.f, 0.f, -1.f, 0.f};
    const float S2[8] = {0.f, 1.f, 0.f, -1.f, 0.f, 1.f, 0.f, -1.f};
    const float C3[8] = {1.f, -SQH, 0.f, SQH, -1.f, SQH, 0.f, -SQH};
    const float S3[8] = {0.f, SQH, -1.f, SQH, 0.f, -SQH, 1.f, -SQH};

#pragma unroll
    for (int r = 0; r < 8; r++) {
        float sg = (r & 1) ? -1.f : 1.f;
        float4 w;
        float res[4];
#pragma unroll
        for (int i = 0; i < 4; i++) {
            res[i] = 0.125f * (v[0][i] + sg * v[1][i])
                   + 0.25f * (C1[r] * v[2][i] - S1[r] * v[3][i]
                            + C2[r] * v[4][i] - S2[r] * v[5][i]
                            + C3[r] * v[6][i] - S3[r] * v[7][i]) + bs[i];
        }
        w.x = res[0]; w.y = res[1]; w.z = res[2]; w.w = res[3];
        stg_cs_v4(&op[(size_t)r * (Nn * Oo)], w);
    }
}

// ---------------------------------------------------------------------------
extern "C" void kernel_launch(void* const* d_in, const int* in_sizes, int n_in,
                              void* d_out, int out_size) {
    const float* signal  = (const float*)d_in[0];
    const float* bary    = (const float*)d_in[1];
    const float* kernels = (const float*)d_in[2];
    const float* bias    = (const float*)d_in[3];
    float* out = (float*)d_out;

    // merged preps: 512 wb blocks + 1000 signal-conversion blocks (320000 float4)
    prep_all_kernel<<<512 + 1000, 320>>>(signal, kernels, bias);

    gather_fft_kernel<<<Mdim / 32, 256>>>(bary);

    {
        static int smem_set = 0;
        if (!smem_set) {
            cudaFuncSetAttribute(gemm_mma_kernel,
                                 cudaFuncAttributeMaxDynamicSharedMemorySize, GEMM_SMEM);
            smem_set = 1;
        }
        dim3 grid(NBLK, Mpad / 128);   // (4, 313)
        gemm_mma_kernel<<<grid, 256, GEMM_SMEM>>>();
    }

    // warp = 2 m rows -> 16 m per CTA -> 2500 blocks
    combine_kernel<<<Mdim / 16, 256>>>(out);
}